// round 13
// baseline (speedup 1.0000x reference)
#include <cuda_runtime.h>
#include <cstdint>

#define NB 4
#define NPTS 262144
#define NPTS_LOG2 18
#define KTOP 6000
#define CAP 16384
#define NOUT 1000
#define NBINS 65536
#define NSEG 32
#define SEGCAP 2048
#define SMASK 2048           // rows covered by precomputed mask
#define MWORDS 32            // SMASK/64 suppression words per row
#define NMS_T 1024
#define THR 0.7f
#define PREFCAP 32768
#define PREF_BIN 0x3F70u     // 16-bit bin of 0.9375

// ---------------- device scratch (no allocations allowed) ----------------
__device__ unsigned int g_hist[NB * NBINS];
__device__ unsigned int g_cut[NB];
__device__ unsigned int g_binbase[NB * NSEG];
__device__ unsigned int g_bincnt[NB * NSEG];
__device__ unsigned int g_prefcnt[NB];
__device__ int g_usepref[NB];
__device__ unsigned long long g_pref[NB * PREFCAP];
__device__ unsigned long long g_cand[NB * CAP];
__device__ float4 g_boxes[NB * KTOP];
__device__ unsigned long long g_mask[NB * SMASK * MWORDS];  // 2MB, L2-resident

// ---------------- zero scratch (graph replays reuse it) ----------------
__global__ void k_zero() {
    int i = blockIdx.x * blockDim.x + threadIdx.x;   // 65536 threads, uint4 each
    reinterpret_cast<uint4*>(g_hist)[i] = make_uint4(0, 0, 0, 0);
    if (i < NB) g_prefcnt[i] = 0;
}

// ---------------- histogram + warp-aggregated prefilter append ----------------
// 524288 threads, one float4 each (two fg scores per thread).
__global__ void __launch_bounds__(256) k_hist(const float4* __restrict__ s4) {
    int tid = blockIdx.x * blockDim.x + threadIdx.x;
    float4 q = s4[tid];
    int b = tid >> 17;
    unsigned bits0 = __float_as_uint(q.y);
    unsigned bits1 = __float_as_uint(q.w);
    atomicAdd(&g_hist[b * NBINS + (bits0 >> 16)], 1u);
    atomicAdd(&g_hist[b * NBINS + (bits1 >> 16)], 1u);

    unsigned i0 = (unsigned)(2 * tid) & (NPTS - 1);
    bool c0 = bits0 >= (PREF_BIN << 16);
    bool c1 = bits1 >= (PREF_BIN << 16);
    unsigned m0 = __ballot_sync(0xffffffffu, c0);
    unsigned m1 = __ballot_sync(0xffffffffu, c1);
    int total = __popc(m0) + __popc(m1);
    if (total) {                                    // uniform within warp
        int lane = threadIdx.x & 31;
        unsigned base = 0;
        if (lane == 0) base = atomicAdd(&g_prefcnt[b], (unsigned)total);
        base = __shfl_sync(0xffffffffu, base, 0);
        unsigned lt = (1u << lane) - 1u;
        if (c0) {
            unsigned p = base + __popc(m0 & lt);
            if (p < PREFCAP)
                g_pref[b * PREFCAP + p] = ((unsigned long long)bits0 << 32) | (unsigned)(~i0);
        }
        if (c1) {
            unsigned p = base + __popc(m0) + __popc(m1 & lt);
            if (p < PREFCAP)
                g_pref[b * PREFCAP + p] = ((unsigned long long)bits1 << 32) | (unsigned)(~(i0 + 1));
        }
    }
}

// ---------------- exact cutoff bin + segment offsets, fully parallel ----------------
__global__ void __launch_bounds__(1024) k_cut() {
    __shared__ unsigned s[1024];
    __shared__ unsigned sh64[64];
    __shared__ unsigned hv[NSEG];
    __shared__ unsigned s_cc, s_cut;
    int b = blockIdx.x, t = threadIdx.x;
    const unsigned* h = &g_hist[b * NBINS];

    int w = t >> 5, lane = t & 31;
    for (int ct = w; ct < 1024; ct += 32) {
        unsigned v = h[ct * 64 + lane] + h[ct * 64 + 32 + lane];
        unsigned tot = __reduce_add_sync(0xffffffffu, v);
        if (lane == 0) s[ct] = tot;
    }
    __syncthreads();
    // suffix scan over 1024 chunk sums (Hillis-Steele)
    for (int off = 1; off < 1024; off <<= 1) {
        unsigned add = (t + off < 1024) ? s[t + off] : 0u;
        __syncthreads();
        s[t] += add;
        __syncthreads();
    }
    // cc = max chunk with suffix >= KTOP (s non-increasing; unique writer)
    {
        unsigned nxt = (t < 1023) ? s[t + 1] : 0u;
        if (s[t] >= KTOP && nxt < KTOP) s_cc = (unsigned)t;
    }
    __syncthreads();
    int cc = (int)s_cc;
    unsigned runAbove = (cc < 1023) ? s[cc + 1] : 0u;

    if (t < 64) sh64[t] = h[cc * 64 + t];
    __syncthreads();
    for (int off = 1; off < 64; off <<= 1) {
        unsigned add = 0;
        if (t < 64) add = (t + off < 64) ? sh64[t + off] : 0u;
        __syncthreads();
        if (t < 64) sh64[t] += add;
        __syncthreads();
    }
    if (t < 64) {
        unsigned cur = runAbove + sh64[t];
        unsigned nxt = (t < 63) ? (runAbove + sh64[t + 1]) : runAbove;
        if (cur >= KTOP && nxt < KTOP) s_cut = (unsigned)(cc * 64 + t);
    }
    __syncthreads();
    unsigned cut = s_cut;
    unsigned sufcut = runAbove + sh64[cut - (unsigned)(cc * 64)];   // suffix(cut)

    if (t == 0) {
        g_cut[b] = cut;
        g_usepref[b] = (cut >= PREF_BIN) && (g_prefcnt[b] <= PREFCAP);
    }
    if (t < NSEG) {
        hv[t] = (cut + t < NBINS) ? h[cut + t] : 0u;
        g_bincnt[b * NSEG + t] = 0;
    }
    __syncthreads();
    if (t < 32) {                                   // inclusive warp prefix of hv
        unsigned v = hv[t];
#pragma unroll
        for (int off = 1; off < 32; off <<= 1) {
            unsigned u = __shfl_up_sync(0xffffffffu, v, off);
            if (lane >= off) v += u;
        }
        g_binbase[b * NSEG + t] = sufcut - v;       // = suffix(cut+t+1)
    }
}

// ---------------- compact into rank segments (prefiltered fast path) ----------------
__device__ __forceinline__ void compact_key(int b, unsigned long long key) {
    unsigned bits = (unsigned)(key >> 32);
    unsigned bin = bits >> 16;
    unsigned cut = g_cut[b];
    if (bin >= cut) {
        unsigned s = bin - cut;
        if (s < NSEG) {
            unsigned pos = g_binbase[b * NSEG + s] + atomicAdd(&g_bincnt[b * NSEG + s], 1u);
            if (pos < CAP) g_cand[b * CAP + pos] = key;
        }
    }
}

__global__ void __launch_bounds__(256) k_compact(const float4* __restrict__ s4) {
    int tid = blockIdx.x * blockDim.x + threadIdx.x;
    int b = tid >> 17;
    if (g_usepref[b]) {
        unsigned local = (unsigned)tid & 131071u;
        unsigned n = g_prefcnt[b];
        if (n > PREFCAP) n = PREFCAP;
        if (local < n) compact_key(b, g_pref[b * PREFCAP + local]);
    } else {                                        // exact fallback: full scan
        float4 q = s4[tid];
        unsigned i0 = (unsigned)(2 * tid) & (NPTS - 1);
        compact_key(b, ((unsigned long long)__float_as_uint(q.y) << 32) | (unsigned)(~i0));
        compact_key(b, ((unsigned long long)__float_as_uint(q.w) << 32) | (unsigned)(~(i0 + 1)));
    }
}

// ---------------- per-segment bitonic sort (adaptive pow2 size) + decode ----------------
__global__ void __launch_bounds__(256) k_segsort(const float4* __restrict__ deltas4,
                                                 const float4* __restrict__ anchors4) {
    __shared__ unsigned long long sk[SEGCAP];
    int b = blockIdx.x / NSEG, s = blockIdx.x % NSEG, t = threadIdx.x;
    unsigned base = g_binbase[b * NSEG + s];
    unsigned n = g_bincnt[b * NSEG + s];
    if (n > SEGCAP) n = SEGCAP;
    if (n == 0 || base >= KTOP) return;

    int m = 32;
    while (m < (int)n) m <<= 1;                     // next pow2 >= n

    for (int i = t; i < m; i += 256)
        sk[i] = (i < (int)n) ? g_cand[b * CAP + base + i] : 0ULL;
    __syncthreads();

    for (int k = 2; k <= m; k <<= 1) {
        for (int j = k >> 1; j > 0; j >>= 1) {
            for (int i = t; i < m; i += 256) {
                int ixj = i ^ j;
                if (ixj > i) {
                    unsigned long long a = sk[i], c = sk[ixj];
                    bool sw = ((i & k) == 0) ? (a < c) : (a > c);  // descending
                    if (sw) { sk[i] = c; sk[ixj] = a; }
                }
            }
            __syncthreads();
        }
    }

    int lim = (int)n;
    if ((int)(KTOP - base) < lim) lim = (int)(KTOP - base);
    for (int r = t; r < lim; r += 256) {
        unsigned idx = ~(unsigned)sk[r];
        size_t off = (size_t)b * NPTS + idx;
        float4 aa = anchors4[off];
        float4 dd = deltas4[off];
        float d0 = dd.x * 0.1f, d1 = dd.y * 0.1f, d2 = dd.z * 0.2f, d3 = dd.w * 0.2f;
        float w = aa.z - aa.x, h = aa.w - aa.y;
        float cx = aa.x + 0.5f * w + d0 * w;
        float cy = aa.y + 0.5f * h + d1 * h;
        w = w * expf(d2);
        h = h * expf(d3);
        float4 box;
        box.x = fminf(fmaxf(cx - 0.5f * w, 0.f), 1.f);
        box.y = fminf(fmaxf(cy - 0.5f * h, 0.f), 1.f);
        box.z = fminf(fmaxf(cx + 0.5f * w, 0.f), 1.f);
        box.w = fminf(fmaxf(cy + 0.5f * h, 0.f), 1.f);
        g_boxes[b * KTOP + base + r] = box;
    }
}

// ---------------- IoU comparator (multiply form, no MUFU div) ----------------
__device__ __forceinline__ bool iou_gt(float4 a, float aa, float4 c, float ac) {
    float lx = fmaxf(a.x, c.x), ly = fmaxf(a.y, c.y);
    float rx = fminf(a.z, c.z), ry = fminf(a.w, c.w);
    float iw = fmaxf(rx - lx, 0.f), ih = fmaxf(ry - ly, 0.f);
    float inter = iw * ih;
    return inter > THR * (aa + ac - inter + 1e-12f);
}

// ---------------- parallel mask build: 64x64 tiles, upper triangle only ----------------
__global__ void __launch_bounds__(256) k_mask() {
    int tj = blockIdx.x, ti = blockIdx.y, b = blockIdx.z;
    if (tj < ti) return;
    __shared__ float4 s_rb[64]; __shared__ float s_ra[64];
    __shared__ float4 s_cb[64]; __shared__ float s_ca[64];
    __shared__ unsigned long long s_word[64];
    int t = threadIdx.x;
    const float4* boxes = g_boxes + b * KTOP;
    if (t < 64) {
        float4 r = boxes[ti * 64 + t];
        s_rb[t] = r; s_ra[t] = (r.z - r.x) * (r.w - r.y);
        s_word[t] = 0ULL;
    } else if (t < 128) {
        int j = t - 64;
        float4 c = boxes[tj * 64 + j];
        s_cb[j] = c; s_ca[j] = (c.z - c.x) * (c.w - c.y);
    }
    __syncthreads();
    int i = t & 63, q = t >> 6;
    float4 bi = s_rb[i]; float ai = s_ra[i];
    unsigned long long part = 0ULL;
#pragma unroll
    for (int jj = 0; jj < 16; jj++) {
        int j = q * 16 + jj;
        bool fwd = (ti < tj) || (j > i);
        if (fwd && iou_gt(bi, ai, s_cb[j], s_ca[j]))
            part |= 1ULL << j;
    }
    if (part) atomicOr(&s_word[i], part);
    __syncthreads();
    if (t < 64)
        g_mask[((size_t)b * SMASK + ti * 64 + t) * MWORDS + tj] = s_word[t];
}

// ---------------- merged greedy-over-mask + on-the-fly tail fallback ----------------
__global__ void __launch_bounds__(NMS_T) k_final(float* __restrict__ out) {
    __shared__ unsigned long long s_diag[SMASK + 2];
    __shared__ unsigned long long s_removed[MWORDS];
    __shared__ int s_keptIdx[NOUT];
    __shared__ int s_kc, s_kcOld, s_done;
    // tail
    __shared__ float4 s_kept[NOUT];
    __shared__ float s_karea[NOUT];
    __shared__ float4 s_chunk[64];
    __shared__ float s_carea[64];
    __shared__ unsigned long long s_intra[65];
    __shared__ unsigned long long s_sup;
    __shared__ int s_newCount;
    __shared__ int s_newIdx[64];

    int b = blockIdx.x, t = threadIdx.x;
    const unsigned long long* mask = g_mask + (size_t)b * SMASK * MWORDS;
    float4* out4 = reinterpret_cast<float4*>(out) + b * NOUT;
    const float4* boxes = g_boxes + b * KTOP;

    for (int p = t; p < SMASK; p += NMS_T)
        s_diag[p] = mask[(size_t)p * MWORDS + (p >> 6)];
    if (t < MWORDS) s_removed[t] = 0ULL;
    if (t == 0) { s_kc = 0; s_done = 0; s_diag[SMASK] = 0ULL; }

    int wq = t >> 5, lane = t & 31;
    for (int c = 0; c < MWORDS; c++) {
        __syncthreads();
        if (t == 0) {
            unsigned long long removed = s_removed[c];
            int kc = s_kc; s_kcOld = kc;
            unsigned long long cur = s_diag[c * 64];
            for (int i = 0; i < 64; i++) {
                unsigned long long nxt = s_diag[c * 64 + i + 1];
                if (!((removed >> i) & 1ULL)) {
                    s_keptIdx[kc++] = c * 64 + i;
                    removed |= cur;
                    if (kc == NOUT) { s_done = 1; break; }
                }
                cur = nxt;
            }
            s_kc = kc;
        }
        __syncthreads();
        if (s_done) break;
        // warp wq owns removal word wq: no atomics, shfl OR-reduce
        int kcOld = s_kcOld, ncnt = s_kc - kcOld;
        unsigned long long acc = 0ULL;
        for (int k = lane; k < ncnt; k += 32)
            acc |= mask[(size_t)s_keptIdx[kcOld + k] * MWORDS + wq];
#pragma unroll
        for (int off = 16; off > 0; off >>= 1)
            acc |= __shfl_xor_sync(0xffffffffu, acc, off);
        if (lane == 0 && acc) s_removed[wq] |= acc;
    }
    __syncthreads();
    int kc = s_kc;

    if (kc == NOUT) {                              // normal case: done within SMASK rows
        for (int r = t; r < NOUT; r += NMS_T)
            out4[r] = boxes[s_keptIdx[r]];
        return;
    }

    // ---- rare tail: continue on-the-fly from row SMASK ----
    for (int r = t; r < kc; r += NMS_T) {
        float4 bx = boxes[s_keptIdx[r]];
        s_kept[r] = bx;
        s_karea[r] = (bx.z - bx.x) * (bx.w - bx.y);
        out4[r] = bx;
    }
    if (t == 0) s_done = 0;

    const int nchunks = (KTOP + 63) / 64;
    for (int c = SMASK / 64; c < nchunks; c++) {
        __syncthreads();
        if (s_done) break;
        int base = c * 64;
        int nc = KTOP - base;
        if (nc > 64) nc = 64;

        if (t < 64) {
            float4 bx = (t < nc) ? boxes[base + t] : make_float4(2.f, 2.f, 2.f, 2.f);
            s_chunk[t] = bx;
            s_carea[t] = (bx.z - bx.x) * (bx.w - bx.y);
            s_intra[t] = 0ULL;
        }
        if (t == 0) { s_sup = 0ULL; s_newCount = 0; s_intra[64] = 0ULL; }
        __syncthreads();

        int kcc = s_kc;
        {
            int j = t & 63;
            float4 bj = s_chunk[j];
            float aj = s_carea[j];
            unsigned sup = 0;
#pragma unroll 4
            for (int k = (t >> 6); k < kcc; k += (NMS_T >> 6))
                sup |= (unsigned)iou_gt(s_kept[k], s_karea[k], bj, aj);
            if (sup && j < nc) atomicOr(&s_sup, 1ULL << j);
        }
        for (int p = t; p < 64 * 64; p += NMS_T) {
            int i = p >> 6, j = p & 63;
            if (i < j && j < nc) {
                if (iou_gt(s_chunk[i], s_carea[i], s_chunk[j], s_carea[j]))
                    atomicOr(&s_intra[i], 1ULL << j);
            }
        }
        __syncthreads();

        if (t == 0) {
            unsigned long long removed = s_sup;
            unsigned long long cur = s_intra[0];
            int ncnt = 0;
            for (int i = 0; i < nc; i++) {
                unsigned long long nxt = s_intra[i + 1];
                if (!((removed >> i) & 1ULL)) {
                    s_newIdx[ncnt++] = i;
                    removed |= cur;
                    if (kcc + ncnt == NOUT) { s_done = 1; break; }
                }
                cur = nxt;
            }
            s_newCount = ncnt;
            s_kc = kcc + ncnt;
        }
        __syncthreads();

        int ncnt = s_newCount;
        if (t < ncnt) {
            int i = s_newIdx[t];
            int rank = kcc + t;
            float4 bx = s_chunk[i];
            s_kept[rank] = bx;
            s_karea[rank] = s_carea[i];
            out4[rank] = bx;
        }
    }
    __syncthreads();
    kc = s_kc;
    for (int r = kc + t; r < NOUT; r += NMS_T)
        out4[r] = make_float4(0.f, 0.f, 0.f, 0.f);
}

// ---------------- launch ----------------
extern "C" void kernel_launch(void* const* d_in, const int* in_sizes, int n_in,
                              void* d_out, int out_size) {
    const float4* scores4  = (const float4*)d_in[0];
    const float4* deltas4  = (const float4*)d_in[1];
    const float4* anchors4 = (const float4*)d_in[2];
    float* out = (float*)d_out;

    k_zero<<<256, 256>>>();
    k_hist<<<2048, 256>>>(scores4);
    k_cut<<<NB, 1024>>>();
    k_compact<<<2048, 256>>>(scores4);
    k_segsort<<<NB * NSEG, 256>>>(deltas4, anchors4);
    k_mask<<<dim3(32, 32, NB), 256>>>();
    k_final<<<NB, NMS_T>>>(out);
}

// round 16
// speedup vs baseline: 1.0085x; 1.0085x over previous
#include <cuda_runtime.h>
#include <cstdint>

#define NB 4
#define NPTS 262144
#define NPTS_LOG2 18
#define KTOP 6000
#define CAP 16384
#define NOUT 1000
#define NBINS 65536
#define NSEG 32
#define SEGCAP 2048
#define SMASK 2048           // rows covered by precomputed mask
#define MWORDS 32            // SMASK/64 suppression words per row
#define NMS_T 1024
#define THR 0.7f
#define PREFCAP 32768
#define PREF_BIN 0x3F70u     // 16-bit bin of 0.9375

// ---------------- device scratch (no allocations allowed) ----------------
__device__ unsigned int g_hist[NB * NBINS];
__device__ unsigned int g_cut[NB];
__device__ unsigned int g_binbase[NB * NSEG];
__device__ unsigned int g_bincnt[NB * NSEG];
__device__ unsigned int g_prefcnt[NB];
__device__ int g_usepref[NB];
__device__ unsigned long long g_pref[NB * PREFCAP];
__device__ unsigned long long g_cand[NB * CAP];
__device__ float4 g_boxes[NB * KTOP];
__device__ unsigned long long g_mask[NB * SMASK * MWORDS];  // 2MB, L2-resident

// ---------------- zero scratch (graph replays reuse it) ----------------
__global__ void k_zero() {
    int i = blockIdx.x * blockDim.x + threadIdx.x;   // 65536 threads, uint4 each
    reinterpret_cast<uint4*>(g_hist)[i] = make_uint4(0, 0, 0, 0);
    if (i < NB) g_prefcnt[i] = 0;
}

// ---------------- histogram + block-aggregated prefilter append ----------------
// 524288 threads, one float4 each (two fg scores per thread). Each block maps
// to exactly one batch (512 blocks per batch), so ONE global atomic per block.
__global__ void __launch_bounds__(256) k_hist(const float4* __restrict__ s4) {
    __shared__ unsigned s_wcnt[8];
    __shared__ unsigned s_base;
    int tid = blockIdx.x * blockDim.x + threadIdx.x;
    float4 q = s4[tid];
    int b = tid >> 17;                               // uniform within block
    unsigned bits0 = __float_as_uint(q.y);
    unsigned bits1 = __float_as_uint(q.w);
    atomicAdd(&g_hist[b * NBINS + (bits0 >> 16)], 1u);
    atomicAdd(&g_hist[b * NBINS + (bits1 >> 16)], 1u);

    unsigned i0 = (unsigned)(2 * tid) & (NPTS - 1);
    bool c0 = bits0 >= (PREF_BIN << 16);
    bool c1 = bits1 >= (PREF_BIN << 16);
    unsigned m0 = __ballot_sync(0xffffffffu, c0);
    unsigned m1 = __ballot_sync(0xffffffffu, c1);
    int w = threadIdx.x >> 5, lane = threadIdx.x & 31;
    if (lane == 0) s_wcnt[w] = (unsigned)(__popc(m0) + __popc(m1));
    __syncthreads();
    if (threadIdx.x == 0) {
        unsigned run = 0;
#pragma unroll
        for (int i = 0; i < 8; i++) { unsigned c = s_wcnt[i]; s_wcnt[i] = run; run += c; }
        s_base = run ? atomicAdd(&g_prefcnt[b], run) : 0u;
    }
    __syncthreads();
    unsigned base = s_base + s_wcnt[w];
    unsigned lt = (1u << lane) - 1u;
    if (c0) {
        unsigned p = base + __popc(m0 & lt);
        if (p < PREFCAP)
            g_pref[b * PREFCAP + p] = ((unsigned long long)bits0 << 32) | (unsigned)(~i0);
    }
    if (c1) {
        unsigned p = base + __popc(m0) + __popc(m1 & lt);
        if (p < PREFCAP)
            g_pref[b * PREFCAP + p] = ((unsigned long long)bits1 << 32) | (unsigned)(~(i0 + 1));
    }
}

// ---------------- exact cutoff bin + segment offsets, fully parallel ----------------
__global__ void __launch_bounds__(1024) k_cut() {
    __shared__ unsigned s[1024];
    __shared__ unsigned sh64[64];
    __shared__ unsigned hv[NSEG];
    __shared__ unsigned s_cc, s_cut;
    int b = blockIdx.x, t = threadIdx.x;
    const unsigned* h = &g_hist[b * NBINS];

    int w = t >> 5, lane = t & 31;
    for (int ct = w; ct < 1024; ct += 32) {
        unsigned v = h[ct * 64 + lane] + h[ct * 64 + 32 + lane];
        unsigned tot = __reduce_add_sync(0xffffffffu, v);
        if (lane == 0) s[ct] = tot;
    }
    __syncthreads();
    // suffix scan over 1024 chunk sums (Hillis-Steele)
    for (int off = 1; off < 1024; off <<= 1) {
        unsigned add = (t + off < 1024) ? s[t + off] : 0u;
        __syncthreads();
        s[t] += add;
        __syncthreads();
    }
    // cc = max chunk with suffix >= KTOP (s non-increasing; unique writer)
    {
        unsigned nxt = (t < 1023) ? s[t + 1] : 0u;
        if (s[t] >= KTOP && nxt < KTOP) s_cc = (unsigned)t;
    }
    __syncthreads();
    int cc = (int)s_cc;
    unsigned runAbove = (cc < 1023) ? s[cc + 1] : 0u;

    if (t < 64) sh64[t] = h[cc * 64 + t];
    __syncthreads();
    for (int off = 1; off < 64; off <<= 1) {
        unsigned add = 0;
        if (t < 64) add = (t + off < 64) ? sh64[t + off] : 0u;
        __syncthreads();
        if (t < 64) sh64[t] += add;
        __syncthreads();
    }
    if (t < 64) {
        unsigned cur = runAbove + sh64[t];
        unsigned nxt = (t < 63) ? (runAbove + sh64[t + 1]) : runAbove;
        if (cur >= KTOP && nxt < KTOP) s_cut = (unsigned)(cc * 64 + t);
    }
    __syncthreads();
    unsigned cut = s_cut;
    unsigned sufcut = runAbove + sh64[cut - (unsigned)(cc * 64)];   // suffix(cut)

    if (t == 0) {
        g_cut[b] = cut;
        g_usepref[b] = (cut >= PREF_BIN) && (g_prefcnt[b] <= PREFCAP);
    }
    if (t < NSEG) {
        hv[t] = (cut + t < NBINS) ? h[cut + t] : 0u;
        g_bincnt[b * NSEG + t] = 0;
    }
    __syncthreads();
    if (t < 32) {                                   // inclusive warp prefix of hv
        unsigned v = hv[t];
#pragma unroll
        for (int off = 1; off < 32; off <<= 1) {
            unsigned u = __shfl_up_sync(0xffffffffu, v, off);
            if (lane >= off) v += u;
        }
        g_binbase[b * NSEG + t] = sufcut - v;       // = suffix(cut+t+1)
    }
}

// ---------------- compact into rank segments (prefiltered fast path) ----------------
__device__ __forceinline__ void compact_key(int b, unsigned long long key) {
    unsigned bits = (unsigned)(key >> 32);
    unsigned bin = bits >> 16;
    unsigned cut = g_cut[b];
    if (bin >= cut) {
        unsigned s = bin - cut;
        if (s < NSEG) {
            unsigned pos = g_binbase[b * NSEG + s] + atomicAdd(&g_bincnt[b * NSEG + s], 1u);
            if (pos < CAP) g_cand[b * CAP + pos] = key;
        }
    }
}

__global__ void __launch_bounds__(256) k_compact(const float4* __restrict__ s4) {
    int tid = blockIdx.x * blockDim.x + threadIdx.x;
    int b = tid >> 17;
    if (g_usepref[b]) {
        unsigned local = (unsigned)tid & 131071u;
        unsigned n = g_prefcnt[b];
        if (n > PREFCAP) n = PREFCAP;
        if (local < n) compact_key(b, g_pref[b * PREFCAP + local]);
    } else {                                        // exact fallback: full scan
        float4 q = s4[tid];
        unsigned i0 = (unsigned)(2 * tid) & (NPTS - 1);
        compact_key(b, ((unsigned long long)__float_as_uint(q.y) << 32) | (unsigned)(~i0));
        compact_key(b, ((unsigned long long)__float_as_uint(q.w) << 32) | (unsigned)(~(i0 + 1)));
    }
}

// ---------------- per-segment bitonic sort (adaptive pow2 size) + decode ----------------
__global__ void __launch_bounds__(256) k_segsort(const float4* __restrict__ deltas4,
                                                 const float4* __restrict__ anchors4) {
    __shared__ unsigned long long sk[SEGCAP];
    int b = blockIdx.x / NSEG, s = blockIdx.x % NSEG, t = threadIdx.x;
    unsigned base = g_binbase[b * NSEG + s];
    unsigned n = g_bincnt[b * NSEG + s];
    if (n > SEGCAP) n = SEGCAP;
    if (n == 0 || base >= KTOP) return;

    int m = 32;
    while (m < (int)n) m <<= 1;                     // next pow2 >= n

    for (int i = t; i < m; i += 256)
        sk[i] = (i < (int)n) ? g_cand[b * CAP + base + i] : 0ULL;
    __syncthreads();

    for (int k = 2; k <= m; k <<= 1) {
        for (int j = k >> 1; j > 0; j >>= 1) {
            for (int i = t; i < m; i += 256) {
                int ixj = i ^ j;
                if (ixj > i) {
                    unsigned long long a = sk[i], c = sk[ixj];
                    bool sw = ((i & k) == 0) ? (a < c) : (a > c);  // descending
                    if (sw) { sk[i] = c; sk[ixj] = a; }
                }
            }
            __syncthreads();
        }
    }

    int lim = (int)n;
    if ((int)(KTOP - base) < lim) lim = (int)(KTOP - base);
    for (int r = t; r < lim; r += 256) {
        unsigned idx = ~(unsigned)sk[r];
        size_t off = (size_t)b * NPTS + idx;
        float4 aa = anchors4[off];
        float4 dd = deltas4[off];
        float d0 = dd.x * 0.1f, d1 = dd.y * 0.1f, d2 = dd.z * 0.2f, d3 = dd.w * 0.2f;
        float w = aa.z - aa.x, h = aa.w - aa.y;
        float cx = aa.x + 0.5f * w + d0 * w;
        float cy = aa.y + 0.5f * h + d1 * h;
        w = w * expf(d2);
        h = h * expf(d3);
        float4 box;
        box.x = fminf(fmaxf(cx - 0.5f * w, 0.f), 1.f);
        box.y = fminf(fmaxf(cy - 0.5f * h, 0.f), 1.f);
        box.z = fminf(fmaxf(cx + 0.5f * w, 0.f), 1.f);
        box.w = fminf(fmaxf(cy + 0.5f * h, 0.f), 1.f);
        g_boxes[b * KTOP + base + r] = box;
    }
}

// ---------------- IoU comparator (multiply form, no MUFU div) ----------------
__device__ __forceinline__ bool iou_gt(float4 a, float aa, float4 c, float ac) {
    float lx = fmaxf(a.x, c.x), ly = fmaxf(a.y, c.y);
    float rx = fminf(a.z, c.z), ry = fminf(a.w, c.w);
    float iw = fmaxf(rx - lx, 0.f), ih = fmaxf(ry - ly, 0.f);
    float inter = iw * ih;
    return inter > THR * (aa + ac - inter + 1e-12f);
}

// ---------------- parallel mask build: 64x64 tiles, upper triangle only ----------------
__global__ void __launch_bounds__(256) k_mask() {
    int tj = blockIdx.x, ti = blockIdx.y, b = blockIdx.z;
    if (tj < ti) return;
    __shared__ float4 s_rb[64]; __shared__ float s_ra[64];
    __shared__ float4 s_cb[64]; __shared__ float s_ca[64];
    __shared__ unsigned long long s_word[64];
    int t = threadIdx.x;
    const float4* boxes = g_boxes + b * KTOP;
    if (t < 64) {
        float4 r = boxes[ti * 64 + t];
        s_rb[t] = r; s_ra[t] = (r.z - r.x) * (r.w - r.y);
        s_word[t] = 0ULL;
    } else if (t < 128) {
        int j = t - 64;
        float4 c = boxes[tj * 64 + j];
        s_cb[j] = c; s_ca[j] = (c.z - c.x) * (c.w - c.y);
    }
    __syncthreads();
    int i = t & 63, q = t >> 6;
    float4 bi = s_rb[i]; float ai = s_ra[i];
    unsigned long long part = 0ULL;
#pragma unroll
    for (int jj = 0; jj < 16; jj++) {
        int j = q * 16 + jj;
        bool fwd = (ti < tj) || (j > i);
        if (fwd && iou_gt(bi, ai, s_cb[j], s_ca[j]))
            part |= 1ULL << j;
    }
    if (part) atomicOr(&s_word[i], part);
    __syncthreads();
    if (t < 64)
        g_mask[((size_t)b * SMASK + ti * 64 + t) * MWORDS + tj] = s_word[t];
}

// ---------------- merged greedy-over-mask + on-the-fly tail fallback ----------------
__global__ void __launch_bounds__(NMS_T) k_final(float* __restrict__ out) {
    __shared__ unsigned long long s_diag[SMASK + 2];
    __shared__ unsigned long long s_removed[MWORDS];
    __shared__ int s_keptIdx[NOUT];
    __shared__ int s_kc, s_kcOld, s_done;
    // tail
    __shared__ float4 s_kept[NOUT];
    __shared__ float s_karea[NOUT];
    __shared__ float4 s_chunk[64];
    __shared__ float s_carea[64];
    __shared__ unsigned long long s_intra[65];
    __shared__ unsigned long long s_sup;
    __shared__ int s_newCount;
    __shared__ int s_newIdx[64];

    int b = blockIdx.x, t = threadIdx.x;
    const unsigned long long* mask = g_mask + (size_t)b * SMASK * MWORDS;
    float4* out4 = reinterpret_cast<float4*>(out) + b * NOUT;
    const float4* boxes = g_boxes + b * KTOP;

    for (int p = t; p < SMASK; p += NMS_T)
        s_diag[p] = mask[(size_t)p * MWORDS + (p >> 6)];
    if (t < MWORDS) s_removed[t] = 0ULL;
    if (t == 0) { s_kc = 0; s_done = 0; s_diag[SMASK] = 0ULL; }

    int wq = t >> 5, lane = t & 31;
    for (int c = 0; c < MWORDS; c++) {
        __syncthreads();
        if (t == 0) {
            unsigned long long removed = s_removed[c];
            int kc = s_kc; s_kcOld = kc;
            unsigned long long cur = s_diag[c * 64];
            for (int i = 0; i < 64; i++) {
                unsigned long long nxt = s_diag[c * 64 + i + 1];
                if (!((removed >> i) & 1ULL)) {
                    s_keptIdx[kc++] = c * 64 + i;
                    removed |= cur;
                    if (kc == NOUT) { s_done = 1; break; }
                }
                cur = nxt;
            }
            s_kc = kc;
        }
        __syncthreads();
        if (s_done) break;
        // warp wq owns removal word wq: no atomics, shfl OR-reduce
        int kcOld = s_kcOld, ncnt = s_kc - kcOld;
        unsigned long long acc = 0ULL;
        for (int k = lane; k < ncnt; k += 32)
            acc |= mask[(size_t)s_keptIdx[kcOld + k] * MWORDS + wq];
#pragma unroll
        for (int off = 16; off > 0; off >>= 1)
            acc |= __shfl_xor_sync(0xffffffffu, acc, off);
        if (lane == 0 && acc) s_removed[wq] |= acc;
    }
    __syncthreads();
    int kc = s_kc;

    if (kc == NOUT) {                              // normal case: done within SMASK rows
        for (int r = t; r < NOUT; r += NMS_T)
            out4[r] = boxes[s_keptIdx[r]];
        return;
    }

    // ---- rare tail: continue on-the-fly from row SMASK ----
    for (int r = t; r < kc; r += NMS_T) {
        float4 bx = boxes[s_keptIdx[r]];
        s_kept[r] = bx;
        s_karea[r] = (bx.z - bx.x) * (bx.w - bx.y);
        out4[r] = bx;
    }
    if (t == 0) s_done = 0;

    const int nchunks = (KTOP + 63) / 64;
    for (int c = SMASK / 64; c < nchunks; c++) {
        __syncthreads();
        if (s_done) break;
        int base = c * 64;
        int nc = KTOP - base;
        if (nc > 64) nc = 64;

        if (t < 64) {
            float4 bx = (t < nc) ? boxes[base + t] : make_float4(2.f, 2.f, 2.f, 2.f);
            s_chunk[t] = bx;
            s_carea[t] = (bx.z - bx.x) * (bx.w - bx.y);
            s_intra[t] = 0ULL;
        }
        if (t == 0) { s_sup = 0ULL; s_newCount = 0; s_intra[64] = 0ULL; }
        __syncthreads();

        int kcc = s_kc;
        {
            int j = t & 63;
            float4 bj = s_chunk[j];
            float aj = s_carea[j];
            unsigned sup = 0;
#pragma unroll 4
            for (int k = (t >> 6); k < kcc; k += (NMS_T >> 6))
                sup |= (unsigned)iou_gt(s_kept[k], s_karea[k], bj, aj);
            if (sup && j < nc) atomicOr(&s_sup, 1ULL << j);
        }
        for (int p = t; p < 64 * 64; p += NMS_T) {
            int i = p >> 6, j = p & 63;
            if (i < j && j < nc) {
                if (iou_gt(s_chunk[i], s_carea[i], s_chunk[j], s_carea[j]))
                    atomicOr(&s_intra[i], 1ULL << j);
            }
        }
        __syncthreads();

        if (t == 0) {
            unsigned long long removed = s_sup;
            unsigned long long cur = s_intra[0];
            int ncnt = 0;
            for (int i = 0; i < nc; i++) {
                unsigned long long nxt = s_intra[i + 1];
                if (!((removed >> i) & 1ULL)) {
                    s_newIdx[ncnt++] = i;
                    removed |= cur;
                    if (kcc + ncnt == NOUT) { s_done = 1; break; }
                }
                cur = nxt;
            }
            s_newCount = ncnt;
            s_kc = kcc + ncnt;
        }
        __syncthreads();

        int ncnt = s_newCount;
        if (t < ncnt) {
            int i = s_newIdx[t];
            int rank = kcc + t;
            float4 bx = s_chunk[i];
            s_kept[rank] = bx;
            s_karea[rank] = s_carea[i];
            out4[rank] = bx;
        }
    }
    __syncthreads();
    kc = s_kc;
    for (int r = kc + t; r < NOUT; r += NMS_T)
        out4[r] = make_float4(0.f, 0.f, 0.f, 0.f);
}

// ---------------- launch ----------------
extern "C" void kernel_launch(void* const* d_in, const int* in_sizes, int n_in,
                              void* d_out, int out_size) {
    const float4* scores4  = (const float4*)d_in[0];
    const float4* deltas4  = (const float4*)d_in[1];
    const float4* anchors4 = (const float4*)d_in[2];
    float* out = (float*)d_out;

    k_zero<<<256, 256>>>();
    k_hist<<<2048, 256>>>(scores4);
    k_cut<<<NB, 1024>>>();
    k_compact<<<2048, 256>>>(scores4);
    k_segsort<<<NB * NSEG, 256>>>(deltas4, anchors4);
    k_mask<<<dim3(32, 32, NB), 256>>>();
    k_final<<<NB, NMS_T>>>(out);
}

// round 17
// speedup vs baseline: 1.0604x; 1.0515x over previous
#include <cuda_runtime.h>
#include <cstdint>

#define NB 4
#define NPTS 262144
#define NPTS_LOG2 18
#define KTOP 6000
#define CAP 16384
#define NOUT 1000
#define NBINS 65536
#define NSEG 32
#define SEGCAP 2048
#define SMASK 2048           // rows covered by precomputed mask
#define MWORDS 32            // SMASK/64 suppression words per row
#define NMS_T 1024
#define THR 0.7f

// ---------------- device scratch (no allocations allowed) ----------------
__device__ unsigned int g_hist[NB * NBINS];          // zeroed by k_mask each run
__device__ unsigned int g_cut[NB];
__device__ unsigned int g_binbase[NB * NSEG];
__device__ unsigned int g_bincnt[NB * NSEG];
__device__ unsigned long long g_cand[NB * CAP];
__device__ float4 g_boxes[NB * KTOP];
__device__ unsigned long long g_mask[NB * SMASK * MWORDS];  // 2MB, L2-resident

// ---------------- histogram of top-16 float bits of fg score ----------------
// 524288 threads, one float4 each (two fg scores per thread).
__global__ void __launch_bounds__(256) k_hist(const float4* __restrict__ s4) {
    int tid = blockIdx.x * blockDim.x + threadIdx.x;
    float4 q = s4[tid];
    int b = tid >> 17;
    atomicAdd(&g_hist[b * NBINS + (__float_as_uint(q.y) >> 16)], 1u);
    atomicAdd(&g_hist[b * NBINS + (__float_as_uint(q.w) >> 16)], 1u);
}

// ---------------- exact cutoff bin + segment offsets, fully parallel ----------------
__global__ void __launch_bounds__(1024) k_cut() {
    __shared__ unsigned s[1024];
    __shared__ unsigned sh64[64];
    __shared__ unsigned hv[NSEG];
    __shared__ unsigned s_cc, s_cut;
    int b = blockIdx.x, t = threadIdx.x;
    const unsigned* h = &g_hist[b * NBINS];

    int w = t >> 5, lane = t & 31;
    for (int ct = w; ct < 1024; ct += 32) {
        unsigned v = h[ct * 64 + lane] + h[ct * 64 + 32 + lane];
        unsigned tot = __reduce_add_sync(0xffffffffu, v);
        if (lane == 0) s[ct] = tot;
    }
    __syncthreads();
    // suffix scan over 1024 chunk sums (Hillis-Steele)
    for (int off = 1; off < 1024; off <<= 1) {
        unsigned add = (t + off < 1024) ? s[t + off] : 0u;
        __syncthreads();
        s[t] += add;
        __syncthreads();
    }
    // cc = max chunk with suffix >= KTOP (s non-increasing; unique writer)
    {
        unsigned nxt = (t < 1023) ? s[t + 1] : 0u;
        if (s[t] >= KTOP && nxt < KTOP) s_cc = (unsigned)t;
    }
    __syncthreads();
    int cc = (int)s_cc;
    unsigned runAbove = (cc < 1023) ? s[cc + 1] : 0u;

    if (t < 64) sh64[t] = h[cc * 64 + t];
    __syncthreads();
    for (int off = 1; off < 64; off <<= 1) {
        unsigned add = 0;
        if (t < 64) add = (t + off < 64) ? sh64[t + off] : 0u;
        __syncthreads();
        if (t < 64) sh64[t] += add;
        __syncthreads();
    }
    if (t < 64) {
        unsigned cur = runAbove + sh64[t];
        unsigned nxt = (t < 63) ? (runAbove + sh64[t + 1]) : runAbove;
        if (cur >= KTOP && nxt < KTOP) s_cut = (unsigned)(cc * 64 + t);
    }
    __syncthreads();
    unsigned cut = s_cut;
    unsigned sufcut = runAbove + sh64[cut - (unsigned)(cc * 64)];   // suffix(cut)

    if (t == 0) g_cut[b] = cut;
    if (t < NSEG) {
        hv[t] = (cut + t < NBINS) ? h[cut + t] : 0u;
        g_bincnt[b * NSEG + t] = 0;
    }
    __syncthreads();
    if (t < 32) {                                   // inclusive warp prefix of hv
        unsigned v = hv[t];
#pragma unroll
        for (int off = 1; off < 32; off <<= 1) {
            unsigned u = __shfl_up_sync(0xffffffffu, v, off);
            if (lane >= off) v += u;
        }
        g_binbase[b * NSEG + t] = sufcut - v;       // = suffix(cut+t+1)
    }
}

// ---------------- compact: scatter candidates straight into rank segments ----------------
__device__ __forceinline__ void compact_one(int b, unsigned i, unsigned bits) {
    unsigned bin = bits >> 16;
    unsigned cut = g_cut[b];
    if (bin >= cut) {
        unsigned s = bin - cut;
        if (s < NSEG) {
            unsigned pos = g_binbase[b * NSEG + s] + atomicAdd(&g_bincnt[b * NSEG + s], 1u);
            if (pos < CAP)
                g_cand[b * CAP + pos] = ((unsigned long long)bits << 32) | (unsigned)(~i);
        }
    }
}

__global__ void __launch_bounds__(256) k_compact(const float4* __restrict__ s4) {
    int tid = blockIdx.x * blockDim.x + threadIdx.x;
    float4 q = s4[tid];
    int b = tid >> 17;
    unsigned i0 = (unsigned)(2 * tid) & (NPTS - 1);
    compact_one(b, i0,     __float_as_uint(q.y));
    compact_one(b, i0 + 1, __float_as_uint(q.w));
}

// ---------------- per-segment bitonic sort (adaptive pow2 size) + decode ----------------
__global__ void __launch_bounds__(256) k_segsort(const float4* __restrict__ deltas4,
                                                 const float4* __restrict__ anchors4) {
    __shared__ unsigned long long sk[SEGCAP];
    int b = blockIdx.x / NSEG, s = blockIdx.x % NSEG, t = threadIdx.x;
    unsigned base = g_binbase[b * NSEG + s];
    unsigned n = g_bincnt[b * NSEG + s];
    if (n > SEGCAP) n = SEGCAP;
    if (n == 0 || base >= KTOP) return;

    int m = 32;
    while (m < (int)n) m <<= 1;                     // next pow2 >= n

    for (int i = t; i < m; i += 256)
        sk[i] = (i < (int)n) ? g_cand[b * CAP + base + i] : 0ULL;
    __syncthreads();

    for (int k = 2; k <= m; k <<= 1) {
        for (int j = k >> 1; j > 0; j >>= 1) {
            for (int i = t; i < m; i += 256) {
                int ixj = i ^ j;
                if (ixj > i) {
                    unsigned long long a = sk[i], c = sk[ixj];
                    bool sw = ((i & k) == 0) ? (a < c) : (a > c);  // descending
                    if (sw) { sk[i] = c; sk[ixj] = a; }
                }
            }
            __syncthreads();
        }
    }

    int lim = (int)n;
    if ((int)(KTOP - base) < lim) lim = (int)(KTOP - base);
    for (int r = t; r < lim; r += 256) {
        unsigned idx = ~(unsigned)sk[r];
        size_t off = (size_t)b * NPTS + idx;
        float4 aa = anchors4[off];
        float4 dd = deltas4[off];
        float d0 = dd.x * 0.1f, d1 = dd.y * 0.1f, d2 = dd.z * 0.2f, d3 = dd.w * 0.2f;
        float w = aa.z - aa.x, h = aa.w - aa.y;
        float cx = aa.x + 0.5f * w + d0 * w;
        float cy = aa.y + 0.5f * h + d1 * h;
        w = w * expf(d2);
        h = h * expf(d3);
        float4 box;
        box.x = fminf(fmaxf(cx - 0.5f * w, 0.f), 1.f);
        box.y = fminf(fmaxf(cy - 0.5f * h, 0.f), 1.f);
        box.z = fminf(fmaxf(cx + 0.5f * w, 0.f), 1.f);
        box.w = fminf(fmaxf(cy + 0.5f * h, 0.f), 1.f);
        g_boxes[b * KTOP + base + r] = box;
    }
}

// ---------------- IoU comparator (multiply form, no MUFU div) ----------------
__device__ __forceinline__ bool iou_gt(float4 a, float aa, float4 c, float ac) {
    float lx = fmaxf(a.x, c.x), ly = fmaxf(a.y, c.y);
    float rx = fminf(a.z, c.z), ry = fminf(a.w, c.w);
    float iw = fmaxf(rx - lx, 0.f), ih = fmaxf(ry - ly, 0.f);
    float inter = iw * ih;
    return inter > THR * (aa + ac - inter + 1e-12f);
}

// ---------------- mask build (also zeroes g_hist for the next graph replay) ----------------
// grid (tj=x 0..31, ti=y 0..31, b=z), 256 threads. Hist is dead after k_cut,
// so the first 256 linear blocks rewrite it to zero here (saves a launch).
__global__ void __launch_bounds__(256) k_mask() {
    int tj = blockIdx.x, ti = blockIdx.y, b = blockIdx.z;
    {
        int bid = (blockIdx.z * 32 + blockIdx.y) * 32 + blockIdx.x;
        int i = bid * 256 + threadIdx.x;
        if (i < NB * NBINS / 4)
            reinterpret_cast<uint4*>(g_hist)[i] = make_uint4(0, 0, 0, 0);
    }
    if (tj < ti) return;
    __shared__ float4 s_rb[64]; __shared__ float s_ra[64];
    __shared__ float4 s_cb[64]; __shared__ float s_ca[64];
    __shared__ unsigned long long s_word[64];
    int t = threadIdx.x;
    const float4* boxes = g_boxes + b * KTOP;
    if (t < 64) {
        float4 r = boxes[ti * 64 + t];
        s_rb[t] = r; s_ra[t] = (r.z - r.x) * (r.w - r.y);
        s_word[t] = 0ULL;
    } else if (t < 128) {
        int j = t - 64;
        float4 c = boxes[tj * 64 + j];
        s_cb[j] = c; s_ca[j] = (c.z - c.x) * (c.w - c.y);
    }
    __syncthreads();
    int i = t & 63, q = t >> 6;
    float4 bi = s_rb[i]; float ai = s_ra[i];
    unsigned long long part = 0ULL;
#pragma unroll
    for (int jj = 0; jj < 16; jj++) {
        int j = q * 16 + jj;
        bool fwd = (ti < tj) || (j > i);
        if (fwd && iou_gt(bi, ai, s_cb[j], s_ca[j]))
            part |= 1ULL << j;
    }
    if (part) atomicOr(&s_word[i], part);
    __syncthreads();
    if (t < 64)
        g_mask[((size_t)b * SMASK + ti * 64 + t) * MWORDS + tj] = s_word[t];
}

// ---------------- merged greedy-over-mask + on-the-fly tail fallback ----------------
__global__ void __launch_bounds__(NMS_T) k_final(float* __restrict__ out) {
    __shared__ unsigned long long s_diag[SMASK + 2];
    __shared__ unsigned long long s_removed[MWORDS];
    __shared__ int s_keptIdx[NOUT];
    __shared__ int s_kc, s_kcOld, s_done;
    // tail
    __shared__ float4 s_kept[NOUT];
    __shared__ float s_karea[NOUT];
    __shared__ float4 s_chunk[64];
    __shared__ float s_carea[64];
    __shared__ unsigned long long s_intra[65];
    __shared__ unsigned long long s_sup;
    __shared__ int s_newCount;
    __shared__ int s_newIdx[64];

    int b = blockIdx.x, t = threadIdx.x;
    const unsigned long long* mask = g_mask + (size_t)b * SMASK * MWORDS;
    float4* out4 = reinterpret_cast<float4*>(out) + b * NOUT;
    const float4* boxes = g_boxes + b * KTOP;

    for (int p = t; p < SMASK; p += NMS_T)
        s_diag[p] = mask[(size_t)p * MWORDS + (p >> 6)];
    if (t < MWORDS) s_removed[t] = 0ULL;
    if (t == 0) { s_kc = 0; s_done = 0; s_diag[SMASK] = 0ULL; }

    for (int c = 0; c < MWORDS; c++) {
        __syncthreads();
        if (t == 0) {
            unsigned long long removed = s_removed[c];
            int kc = s_kc; s_kcOld = kc;
            unsigned long long cur = s_diag[c * 64];
            for (int i = 0; i < 64; i++) {
                unsigned long long nxt = s_diag[c * 64 + i + 1];
                if (!((removed >> i) & 1ULL)) {
                    s_keptIdx[kc++] = c * 64 + i;
                    removed |= cur;
                    if (kc == NOUT) { s_done = 1; break; }
                }
                cur = nxt;
            }
            s_kc = kc;
        }
        __syncthreads();
        if (s_done) break;
        // OR the newly-kept rows' mask words into the removal bitvector
        int kcOld = s_kcOld, ncnt = s_kc - kcOld;
        for (int p = t; p < ncnt * MWORDS; p += NMS_T) {
            int k = p >> 5, w = p & (MWORDS - 1);
            int row = s_keptIdx[kcOld + k];
            unsigned long long m = mask[(size_t)row * MWORDS + w];
            if (m) atomicOr(&s_removed[w], m);
        }
    }
    __syncthreads();
    int kc = s_kc;

    if (kc == NOUT) {                              // normal case: done within SMASK rows
        for (int r = t; r < NOUT; r += NMS_T)
            out4[r] = boxes[s_keptIdx[r]];
        return;
    }

    // ---- rare tail: continue on-the-fly from row SMASK ----
    for (int r = t; r < kc; r += NMS_T) {
        float4 bx = boxes[s_keptIdx[r]];
        s_kept[r] = bx;
        s_karea[r] = (bx.z - bx.x) * (bx.w - bx.y);
        out4[r] = bx;
    }
    if (t == 0) s_done = 0;

    const int nchunks = (KTOP + 63) / 64;
    for (int c = SMASK / 64; c < nchunks; c++) {
        __syncthreads();
        if (s_done) break;
        int base = c * 64;
        int nc = KTOP - base;
        if (nc > 64) nc = 64;

        if (t < 64) {
            float4 bx = (t < nc) ? boxes[base + t] : make_float4(2.f, 2.f, 2.f, 2.f);
            s_chunk[t] = bx;
            s_carea[t] = (bx.z - bx.x) * (bx.w - bx.y);
            s_intra[t] = 0ULL;
        }
        if (t == 0) { s_sup = 0ULL; s_newCount = 0; s_intra[64] = 0ULL; }
        __syncthreads();

        int kcc = s_kc;
        {
            int j = t & 63;
            float4 bj = s_chunk[j];
            float aj = s_carea[j];
            unsigned sup = 0;
#pragma unroll 4
            for (int k = (t >> 6); k < kcc; k += (NMS_T >> 6))
                sup |= (unsigned)iou_gt(s_kept[k], s_karea[k], bj, aj);
            if (sup && j < nc) atomicOr(&s_sup, 1ULL << j);
        }
        for (int p = t; p < 64 * 64; p += NMS_T) {
            int i = p >> 6, j = p & 63;
            if (i < j && j < nc) {
                if (iou_gt(s_chunk[i], s_carea[i], s_chunk[j], s_carea[j]))
                    atomicOr(&s_intra[i], 1ULL << j);
            }
        }
        __syncthreads();

        if (t == 0) {
            unsigned long long removed = s_sup;
            unsigned long long cur = s_intra[0];
            int ncnt = 0;
            for (int i = 0; i < nc; i++) {
                unsigned long long nxt = s_intra[i + 1];
                if (!((removed >> i) & 1ULL)) {
                    s_newIdx[ncnt++] = i;
                    removed |= cur;
                    if (kcc + ncnt == NOUT) { s_done = 1; break; }
                }
                cur = nxt;
            }
            s_newCount = ncnt;
            s_kc = kcc + ncnt;
        }
        __syncthreads();

        int ncnt = s_newCount;
        if (t < ncnt) {
            int i = s_newIdx[t];
            int rank = kcc + t;
            float4 bx = s_chunk[i];
            s_kept[rank] = bx;
            s_karea[rank] = s_carea[i];
            out4[rank] = bx;
        }
    }
    __syncthreads();
    kc = s_kc;
    for (int r = kc + t; r < NOUT; r += NMS_T)
        out4[r] = make_float4(0.f, 0.f, 0.f, 0.f);
}

// ---------------- launch ----------------
extern "C" void kernel_launch(void* const* d_in, const int* in_sizes, int n_in,
                              void* d_out, int out_size) {
    const float4* scores4  = (const float4*)d_in[0];
    const float4* deltas4  = (const float4*)d_in[1];
    const float4* anchors4 = (const float4*)d_in[2];
    float* out = (float*)d_out;

    k_hist<<<2048, 256>>>(scores4);
    k_cut<<<NB, 1024>>>();
    k_compact<<<2048, 256>>>(scores4);
    k_segsort<<<NB * NSEG, 256>>>(deltas4, anchors4);
    k_mask<<<dim3(32, 32, NB), 256>>>();
    k_final<<<NB, NMS_T>>>(out);
}